// round 12
// baseline (speedup 1.0000x reference)
#include <cuda_runtime.h>
#include <cuda_bf16.h>
#include <cuda_fp8.h>
#include <stdint.h>

// ---------------- Problem constants ----------------
#define Bc          64
#define MAXT        511
#define TP1         512
#define Sdim        1024
#define Hdim        4096
#define W2LD        32
#define ROWS_TOTAL  (Bc * MAXT)            // 32704
#define W1SCALE     32.0f
#define W1INV       0.03125f

// ---------------- Tiling (fp8: BK = 128 elements = 128 bytes/row) ----------------
#define BM          128
#define BN          256
#define BK          128
#define KT          (Sdim / BK)            // 8
#define NT          (Hdim / BN)            // 16
#define NCHUNK      8
#define NT_PER      (NT / NCHUNK)          // 2
#define NTHREADS    256
#define NTILES      ((ROWS_TOTAL + BM - 1) / BM)   // 256
#define ITERS       (NT_PER * KT)          // 16
#define STAGES      4

// ---------------- SMEM layout ----------------
#define A_BYTES     (BM * BK)              // 16384
#define B_BYTES     (BN * BK)              // 32768
#define STAGE_BYTES (A_BYTES + B_BYTES)    // 49152
#define OFF_LOGIT   (STAGES * STAGE_BYTES) // 196608
#define SMEM_BYTES  (OFF_LOGIT + BM * 4 * 4 + 1024)

// ---------------- device-global scratch ----------------
__device__ __align__(16) uint8_t g_Sbf[(size_t)(ROWS_TOTAL + BM) * Sdim];  // compacted fp8 S
__device__ __align__(16) uint8_t g_W1T[(size_t)Hdim * Sdim];               // fp8 [n][k], pre-scaled x32
__device__ float g_logit[(size_t)ROWS_TOTAL * 4];   // indexed by compact row
__device__ int   g_rowmap[ROWS_TOTAL];              // compact i -> b*TP1 + t
__device__ int   g_nrows;

// ---------------- helpers ----------------
__device__ __forceinline__ uint32_t smem_u32(const void* p) {
    uint32_t a;
    asm("{ .reg .u64 t; cvta.to.shared.u64 t, %1; cvt.u32.u64 %0, t; }" : "=r"(a) : "l"(p));
    return a;
}
__device__ __forceinline__ uint32_t swz(uint32_t bo) { return bo ^ ((bo >> 3) & 0x70); }

#define CP_ASYNC16(dst, src) \
    asm volatile("cp.async.cg.shared.global [%0], [%1], 16;" :: "r"(dst), "l"(src))
#define CP_COMMIT() asm volatile("cp.async.commit_group;")
#define CP_WAIT(n)  asm volatile("cp.async.wait_group %0;" :: "n"(n))

__device__ __forceinline__ void ldsm4(uint32_t (&r)[4], uint32_t addr) {
    asm volatile("ldmatrix.sync.aligned.m8n8.x4.shared.b16 {%0,%1,%2,%3}, [%4];"
                 : "=r"(r[0]), "=r"(r[1]), "=r"(r[2]), "=r"(r[3]) : "r"(addr));
}
// fp8 e4m3 MMA: m16n8k32, fp32 accum
__device__ __forceinline__ void mma_fp8(float (&c)[4], const uint32_t (&a)[4],
                                        uint32_t b0, uint32_t b1) {
    asm volatile("mma.sync.aligned.m16n8k32.row.col.f32.e4m3.e4m3.f32 "
                 "{%0,%1,%2,%3}, {%4,%5,%6,%7}, {%8,%9}, {%0,%1,%2,%3};"
                 : "+f"(c[0]), "+f"(c[1]), "+f"(c[2]), "+f"(c[3])
                 : "r"(a[0]), "r"(a[1]), "r"(a[2]), "r"(a[3]), "r"(b0), "r"(b1));
}
__device__ __forceinline__ uint8_t f2e4m3(float v) {
    return (uint8_t)__nv_cvt_float_to_fp8(v, __NV_SATFINITE, __NV_E4M3);
}

// ---------------- pre-kernels ----------------
// 1) compaction (single block): rowmap + nrows + out zero
__global__ void compact_kernel(const int* __restrict__ lengths, float* __restrict__ out) {
    __shared__ int off[Bc];
    int tid = threadIdx.x;
    if (tid == 0) {
        int a = 0;
        for (int b = 0; b < Bc; ++b) {
            off[b] = a;
            int L = lengths[b]; if (L < 0) L = 0; if (L > MAXT) L = MAXT;
            a += L;
        }
        g_nrows = a;
        out[0] = 0.0f;
    }
    __syncthreads();
    for (int r = tid; r < ROWS_TOTAL; r += blockDim.x) {
        int b = r / MAXT, t = r - b * MAXT;
        if (t < lengths[b]) g_rowmap[off[b] + t] = b * TP1 + t;
    }
}

// 2) convert live S rows -> compacted fp8; also zero g_logit
__global__ void conv_S_compact(const float* __restrict__ S) {
    for (size_t i = (size_t)blockIdx.x * blockDim.x + threadIdx.x; i < (size_t)ROWS_TOTAL * 4;
         i += (size_t)gridDim.x * blockDim.x)
        g_logit[i] = 0.0f;
    const int R = g_nrows;
    size_t n = (size_t)R * (Sdim / 16);          // 16-float units
    for (size_t idx = (size_t)blockIdx.x * blockDim.x + threadIdx.x; idx < n;
         idx += (size_t)gridDim.x * blockDim.x) {
        size_t i = idx >> 6;                     // compact row
        int    u = (int)(idx & 63);              // 16-elem unit within row
        const float4* s4 = (const float4*)(S + (size_t)g_rowmap[i] * Sdim + u * 16);
        uint8_t o[16];
#pragma unroll
        for (int j = 0; j < 4; ++j) {
            float4 v = s4[j];
            o[4 * j + 0] = f2e4m3(v.x); o[4 * j + 1] = f2e4m3(v.y);
            o[4 * j + 2] = f2e4m3(v.z); o[4 * j + 3] = f2e4m3(v.w);
        }
        *(uint4*)(g_Sbf + i * Sdim + u * 16) = *(uint4*)o;
    }
}

// 3) W1 -> transposed fp8 [n][k], pre-scaled by 32
__global__ void conv_W1T_kernel(const float* __restrict__ W1) {
    __shared__ float tile[32][33];
    int n0 = blockIdx.x * 32, k0 = blockIdx.y * 32;
    int x = threadIdx.x, y = threadIdx.y;   // block (32,8)
#pragma unroll
    for (int j = 0; j < 32; j += 8)
        tile[y + j][x] = W1[(size_t)(k0 + y + j) * Hdim + n0 + x];
    __syncthreads();
#pragma unroll
    for (int j = 0; j < 32; j += 8)
        g_W1T[(size_t)(n0 + y + j) * Sdim + k0 + x] = f2e4m3(tile[x][y + j] * W1SCALE);
}

// ---------------- main fused kernel ----------------
__global__ __launch_bounds__(NTHREADS, 1)
void traj_mma_kernel(const float* __restrict__ b1,
                     const float* __restrict__ W2)
{
    const int tid    = threadIdx.x;
    const int tile   = blockIdx.x >> 3;
    const int chunk  = blockIdx.x & 7;
    const int R0     = tile * BM;
    const int ntBase = chunk * NT_PER;

    const int R = g_nrows;
    if (R0 >= R) return;

    extern __shared__ char smraw[];
    uint32_t sb0 = smem_u32(smraw);
    uint32_t sb  = (sb0 + 1023u) & ~1023u;
    char* smp    = smraw + (sb - sb0);

    const int wid = tid >> 5, lid = tid & 31;
    const int wm  = (wid & 1) * 64;          // warp m base (0/64)
    const int wn  = (wid >> 1) * 64;         // warp n base (0/64/128/192)

    // ---- loader constants (byte offsets; fp8 row = 128 B) ----
    const int arow0 = tid >> 3;               // 0..31
    const int acu   = tid & 7;                // 16B unit within 128B row
    uint32_t a_goff[4];
#pragma unroll
    for (int i = 0; i < 4; ++i) {
        int grow = R0 + arow0 + 32 * i;
        if (grow >= R) grow = R - 1;           // clamp; masked at write-out
        a_goff[i] = (uint32_t)grow * Sdim + acu * 16;
    }
    const uint32_t sA0  = swz((uint32_t)(arow0 * 128 + acu * 16));   // +4096*i
    const uint32_t b_g0 = (uint32_t)(arow0 * Sdim + acu * 16);       // +i*32*Sdim
    const uint32_t bNtBase = (uint32_t)(ntBase * BN) * Sdim;

    // ---- fragment address constants (identical mapping to bf16 case) ----
    uint32_t aRow[4], bRow[4];
#pragma unroll
    for (int mi = 0; mi < 4; ++mi)
        aRow[mi] = (uint32_t)((wm + 16 * mi + (lid & 7) + ((lid >> 3) & 1) * 8) * 128);
    const uint32_t aCol = (uint32_t)((lid >> 4) * 16);
#pragma unroll
    for (int s = 0; s < 4; ++s)
        bRow[s] = (uint32_t)((wn + 16 * s + (lid & 7) + ((lid >> 4) & 1) * 8) * 128);
    const uint32_t bCol = (uint32_t)(((lid >> 3) & 1) * 16);

    float p[8][4];
#pragma unroll
    for (int r = 0; r < 8; ++r)
#pragma unroll
        for (int a = 0; a < 4; ++a) p[r][a] = 0.0f;

    float acc[4][8][4];
#pragma unroll
    for (int mi = 0; mi < 4; ++mi)
#pragma unroll
        for (int nj = 0; nj < 8; ++nj)
#pragma unroll
            for (int q = 0; q < 4; ++q) acc[mi][nj][q] = 0.0f;

    auto issue = [&](int it) {
        if (it >= ITERS) return;
        const int nt = it >> 3, kc = it & 7;
        const int st = it & (STAGES - 1);
        const uint32_t sA = sb + st * STAGE_BYTES;
        const uint32_t sB = sA + A_BYTES;
        const uint32_t ko = (uint32_t)kc * BK;
#pragma unroll
        for (int i = 0; i < 4; ++i)
            CP_ASYNC16(sA + sA0 + 4096u * i, (const char*)(g_Sbf + a_goff[i] + ko));
        const uint32_t boff = bNtBase + (uint32_t)(nt * BN) * Sdim + ko + b_g0;
#pragma unroll
        for (int i = 0; i < 8; ++i)
            CP_ASYNC16(sB + sA0 + 4096u * i, (const char*)(g_W1T + boff + (uint32_t)(i * 32) * Sdim));
        CP_COMMIT();
    };

    issue(0); issue(1); issue(2);

    float* logit = (float*)(smp + OFF_LOGIT);
    for (int i = tid; i < BM * 4; i += NTHREADS) logit[i] = 0.0f;

    for (int it = 0; it < ITERS; ++it) {
        CP_WAIT(STAGES - 2);
        __syncthreads();
        issue(it + STAGES - 1);

        const int st = it & (STAGES - 1);
        const uint32_t sA = sb + st * STAGE_BYTES;
        const uint32_t sB = sA + A_BYTES;
#pragma unroll
        for (int ks = 0; ks < 4; ++ks) {      // each ks covers k32 (32 bytes)
            uint32_t afr[4][4], bfr[4][4];
#pragma unroll
            for (int mi = 0; mi < 4; ++mi)
                ldsm4(afr[mi], sA + swz(aRow[mi] + (uint32_t)(ks * 32) + aCol));
#pragma unroll
            for (int s = 0; s < 4; ++s)
                ldsm4(bfr[s], sB + swz(bRow[s] + (uint32_t)(ks * 32) + bCol));
#pragma unroll
            for (int mi = 0; mi < 4; ++mi)
#pragma unroll
                for (int s = 0; s < 4; ++s) {
                    mma_fp8(acc[mi][2 * s    ], afr[mi], bfr[s][0], bfr[s][1]);
                    mma_fp8(acc[mi][2 * s + 1], afr[mi], bfr[s][2], bfr[s][3]);
                }
        }

        // ---- per-nt fused epilogue (undo W1 x32 pre-scale) ----
        if ((it & 7) == 7) {
            const int ntg = ntBase + (it >> 3);
#pragma unroll
            for (int nj = 0; nj < 8; ++nj) {
                const int cbase = ntg * BN + wn + 8 * nj + 2 * (lid & 3);
                const float b1a = __ldg(b1 + cbase);
                const float b1b = __ldg(b1 + cbase + 1);
                float w2a[4], w2b[4];
#pragma unroll
                for (int a = 0; a < 4; ++a) {
                    w2a[a] = __ldg(W2 + (size_t)cbase * W2LD + a);
                    w2b[a] = __ldg(W2 + (size_t)(cbase + 1) * W2LD + a);
                }
#pragma unroll
                for (int mi = 0; mi < 4; ++mi) {
                    float h0 = fmaxf(fmaf(acc[mi][nj][0], W1INV, b1a), 0.0f);
                    float h1 = fmaxf(fmaf(acc[mi][nj][1], W1INV, b1b), 0.0f);
                    float h2 = fmaxf(fmaf(acc[mi][nj][2], W1INV, b1a), 0.0f);
                    float h3 = fmaxf(fmaf(acc[mi][nj][3], W1INV, b1b), 0.0f);
#pragma unroll
                    for (int a = 0; a < 4; ++a) {
                        p[2 * mi    ][a] += h0 * w2a[a] + h1 * w2b[a];
                        p[2 * mi + 1][a] += h2 * w2a[a] + h3 * w2b[a];
                    }
                }
            }
#pragma unroll
            for (int mi = 0; mi < 4; ++mi)
#pragma unroll
                for (int nj = 0; nj < 8; ++nj)
#pragma unroll
                    for (int q = 0; q < 4; ++q) acc[mi][nj][q] = 0.0f;
        }
    }

    // ---- reduce partial logits in smem, then global atomics ----
    __syncthreads();
#pragma unroll
    for (int pr = 0; pr < 8; ++pr) {
        int row = wm + 16 * (pr >> 1) + (lid >> 2) + 8 * (pr & 1);
#pragma unroll
        for (int a = 0; a < 4; ++a)
            atomicAdd(&logit[row * 4 + a], p[pr][a]);
    }
    __syncthreads();
    if (tid < BM && R0 + tid < R) {
#pragma unroll
        for (int a = 0; a < 4; ++a)
            atomicAdd(&g_logit[(size_t)(R0 + tid) * 4 + a], logit[tid * 4 + a]);
    }
}

// ---------------- finalize over compact rows ----------------
__global__ void traj_finalize_kernel(const int* __restrict__ actions,
                                     const float* __restrict__ b2,
                                     float* __restrict__ out)
{
    int i = blockIdx.x * 128 + threadIdx.x;
    float local = 0.0f;
    if (i < g_nrows) {
        int m  = g_rowmap[i];
        int bb = m >> 9;            // TP1 = 512
        int tt = m & 511;
        size_t o = (size_t)i * 4;
        float l0 = g_logit[o + 0] + b2[0];
        float l1 = g_logit[o + 1] + b2[1];
        float l2 = g_logit[o + 2] + b2[2];
        float l3 = g_logit[o + 3] + b2[3];
        float mx = fmaxf(fmaxf(l0, l1), fmaxf(l2, l3));
        float lse = mx + logf(expf(l0 - mx) + expf(l1 - mx) + expf(l2 - mx) + expf(l3 - mx));
        int act = actions[bb * MAXT + tt];
        float la = (act == 0) ? l0 : (act == 1) ? l1 : (act == 2) ? l2 : l3;
        local = lse - la;
    }
#pragma unroll
    for (int o = 16; o > 0; o >>= 1)
        local += __shfl_xor_sync(0xFFFFFFFFu, local, o);
    if ((threadIdx.x & 31) == 0 && local != 0.0f) atomicAdd(out, local);
}

// ---------------- launch ----------------
extern "C" void kernel_launch(void* const* d_in, const int* in_sizes, int n_in,
                              void* d_out, int out_size) {
    const float* s       = (const float*)d_in[0];
    const int*   actions = (const int*)  d_in[1];
    const int*   lengths = (const int*)  d_in[2];
    const float* W1      = (const float*)d_in[3];
    const float* b1      = (const float*)d_in[4];
    const float* W2      = (const float*)d_in[5];
    const float* b2      = (const float*)d_in[6];
    float* out = (float*)d_out;

    cudaFuncSetAttribute(traj_mma_kernel, cudaFuncAttributeMaxDynamicSharedMemorySize, SMEM_BYTES);

    compact_kernel<<<1, 256>>>(lengths, out);
    conv_S_compact<<<2048, 256>>>(s);
    conv_W1T_kernel<<<dim3(Hdim / 32, Sdim / 32), dim3(32, 8)>>>(W1);
    traj_mma_kernel<<<NTILES * NCHUNK, NTHREADS, SMEM_BYTES>>>(b1, W2);
    traj_finalize_kernel<<<(ROWS_TOTAL + 127) / 128, 128>>>(actions, b2, out);
}

// round 13
// speedup vs baseline: 1.2483x; 1.2483x over previous
#include <cuda_runtime.h>
#include <cuda_bf16.h>
#include <stdint.h>

// ---------------- Problem constants ----------------
#define Bc          64
#define MAXT        511
#define TP1         512
#define Sdim        1024
#define Hdim        4096
#define W2LD        32
#define ROWS_TOTAL  (Bc * MAXT)            // 32704

// ---------------- Tiling: 128x128 CTA tile, 4 warps of 64x64, 2 CTAs/SM ----------------
#define BM          128
#define BN          128
#define BK          64
#define KT          (Sdim / BK)            // 16
#define NT          (Hdim / BN)            // 32
#define NCHUNK      16
#define NT_PER      (NT / NCHUNK)          // 2
#define NTHREADS    128
#define NTILES      ((ROWS_TOTAL + BM - 1) / BM)   // 256
#define ITERS       (NT_PER * KT)          // 32
#define STAGES      3

// ---------------- SMEM layout ----------------
#define A_BYTES     (BM * BK * 2)          // 16384
#define B_BYTES     (BN * BK * 2)          // 16384
#define STAGE_BYTES (A_BYTES + B_BYTES)    // 32768
#define OFF_LOGIT   (STAGES * STAGE_BYTES) // 98304
#define SMEM_BYTES  (OFF_LOGIT + BM * 4 * 4 + 1024)   // ~101.4 KB -> 2 CTAs fit in 228 KB

// ---------------- device-global scratch ----------------
__device__ __align__(16) __nv_bfloat16 g_Sbf[(size_t)(ROWS_TOTAL + BM) * Sdim]; // compacted live rows
__device__ __align__(16) __nv_bfloat16 g_W1T[(size_t)Hdim * Sdim];              // [n][k]
__device__ float g_logit[(size_t)ROWS_TOTAL * 4];   // indexed by compact row
__device__ int   g_rowmap[ROWS_TOTAL];              // compact i -> b*TP1 + t
__device__ int   g_nrows;

// ---------------- helpers ----------------
__device__ __forceinline__ uint32_t smem_u32(const void* p) {
    uint32_t a;
    asm("{ .reg .u64 t; cvta.to.shared.u64 t, %1; cvt.u32.u64 %0, t; }" : "=r"(a) : "l"(p));
    return a;
}
__device__ __forceinline__ uint32_t swz(uint32_t bo) { return bo ^ ((bo >> 3) & 0x70); }

#define CP_ASYNC16(dst, src) \
    asm volatile("cp.async.cg.shared.global [%0], [%1], 16;" :: "r"(dst), "l"(src))
#define CP_COMMIT() asm volatile("cp.async.commit_group;")
#define CP_WAIT(n)  asm volatile("cp.async.wait_group %0;" :: "n"(n))

__device__ __forceinline__ void ldsm4(uint32_t (&r)[4], uint32_t addr) {
    asm volatile("ldmatrix.sync.aligned.m8n8.x4.shared.b16 {%0,%1,%2,%3}, [%4];"
                 : "=r"(r[0]), "=r"(r[1]), "=r"(r[2]), "=r"(r[3]) : "r"(addr));
}
__device__ __forceinline__ void mma16816(float (&c)[4], const uint32_t (&a)[4],
                                         uint32_t b0, uint32_t b1) {
    asm volatile("mma.sync.aligned.m16n8k16.row.col.f32.bf16.bf16.f32 "
                 "{%0,%1,%2,%3}, {%4,%5,%6,%7}, {%8,%9}, {%0,%1,%2,%3};"
                 : "+f"(c[0]), "+f"(c[1]), "+f"(c[2]), "+f"(c[3])
                 : "r"(a[0]), "r"(a[1]), "r"(a[2]), "r"(a[3]), "r"(b0), "r"(b1));
}

// ---------------- pre-kernels ----------------
__global__ void compact_kernel(const int* __restrict__ lengths, float* __restrict__ out) {
    __shared__ int off[Bc];
    int tid = threadIdx.x;
    if (tid == 0) {
        int a = 0;
        for (int b = 0; b < Bc; ++b) {
            off[b] = a;
            int L = lengths[b]; if (L < 0) L = 0; if (L > MAXT) L = MAXT;
            a += L;
        }
        g_nrows = a;
        out[0] = 0.0f;
    }
    __syncthreads();
    for (int r = tid; r < ROWS_TOTAL; r += blockDim.x) {
        int b = r / MAXT, t = r - b * MAXT;
        if (t < lengths[b]) g_rowmap[off[b] + t] = b * TP1 + t;
    }
}

__global__ void conv_S_compact(const float* __restrict__ S) {
    for (size_t i = (size_t)blockIdx.x * blockDim.x + threadIdx.x; i < (size_t)ROWS_TOTAL * 4;
         i += (size_t)gridDim.x * blockDim.x)
        g_logit[i] = 0.0f;
    const int R = g_nrows;
    size_t n = (size_t)R * (Sdim / 8);           // 8-float units
    for (size_t idx = (size_t)blockIdx.x * blockDim.x + threadIdx.x; idx < n;
         idx += (size_t)gridDim.x * blockDim.x) {
        size_t i = idx >> 7;                     // compact row
        int    u = (int)(idx & 127);             // unit within row
        const float4* s4 = (const float4*)(S + (size_t)g_rowmap[i] * Sdim + u * 8);
        float4 v0 = s4[0], v1 = s4[1];
        __nv_bfloat162 p0 = __floats2bfloat162_rn(v0.x, v0.y);
        __nv_bfloat162 p1 = __floats2bfloat162_rn(v0.z, v0.w);
        __nv_bfloat162 p2 = __floats2bfloat162_rn(v1.x, v1.y);
        __nv_bfloat162 p3 = __floats2bfloat162_rn(v1.z, v1.w);
        uint4 o;
        o.x = *(uint32_t*)&p0; o.y = *(uint32_t*)&p1;
        o.z = *(uint32_t*)&p2; o.w = *(uint32_t*)&p3;
        *(uint4*)(g_Sbf + i * Sdim + u * 8) = o;
    }
}

__global__ void conv_W1T_kernel(const float* __restrict__ W1) {
    __shared__ float tile[32][33];
    int n0 = blockIdx.x * 32, k0 = blockIdx.y * 32;
    int x = threadIdx.x, y = threadIdx.y;   // block (32,8)
#pragma unroll
    for (int j = 0; j < 32; j += 8)
        tile[y + j][x] = W1[(size_t)(k0 + y + j) * Hdim + n0 + x];
    __syncthreads();
#pragma unroll
    for (int j = 0; j < 32; j += 8)
        g_W1T[(size_t)(n0 + y + j) * Sdim + k0 + x] = __float2bfloat16(tile[x][y + j]);
}

// ---------------- main fused kernel (128 threads, 2 CTAs/SM) ----------------
__global__ __launch_bounds__(NTHREADS, 2)
void traj_mma_kernel(const float* __restrict__ b1,
                     const float* __restrict__ W2)
{
    const int tid    = threadIdx.x;
    const int tile   = blockIdx.x >> 4;
    const int chunk  = blockIdx.x & 15;
    const int R0     = tile * BM;
    const int ntBase = chunk * NT_PER;

    const int R = g_nrows;
    if (R0 >= R) return;

    extern __shared__ char smraw[];
    uint32_t sb0 = smem_u32(smraw);
    uint32_t sb  = (sb0 + 1023u) & ~1023u;
    char* smp    = smraw + (sb - sb0);

    const int wid = tid >> 5, lid = tid & 31;
    const int wm  = (wid & 1) * 64;          // warp m base (0/64)
    const int wn  = (wid >> 1) * 64;         // warp n base (0/64)

    // ---- loader constants: 1024 16B units per operand, 128 threads -> 8/thread ----
    const int arow0 = tid >> 3;               // 0..15
    const int acu   = tid & 7;
    uint32_t a_goff[8];
#pragma unroll
    for (int i = 0; i < 8; ++i) {
        int grow = R0 + arow0 + 16 * i;
        if (grow >= R) grow = R - 1;           // clamp; masked at write-out
        a_goff[i] = (uint32_t)grow * Sdim + acu * 8;
    }
    const uint32_t sA0  = swz((uint32_t)(arow0 * 128 + acu * 16));   // +2048*i (row+16 keeps swizzle bits)
    const uint32_t b_g0 = (uint32_t)(arow0 * Sdim + acu * 8);        // +i*16*Sdim
    const uint32_t bNtBase = (uint32_t)(ntBase * BN) * Sdim;

    // ---- fragment address constants ----
    uint32_t aRow[4], bRow[4];
#pragma unroll
    for (int mi = 0; mi < 4; ++mi)
        aRow[mi] = (uint32_t)((wm + 16 * mi + (lid & 7) + ((lid >> 3) & 1) * 8) * 128);
    const uint32_t aCol = (uint32_t)((lid >> 4) * 16);
#pragma unroll
    for (int s = 0; s < 4; ++s)
        bRow[s] = (uint32_t)((wn + 16 * s + (lid & 7) + ((lid >> 4) & 1) * 8) * 128);
    const uint32_t bCol = (uint32_t)(((lid >> 3) & 1) * 16);

    float p[8][4];
#pragma unroll
    for (int r = 0; r < 8; ++r)
#pragma unroll
        for (int a = 0; a < 4; ++a) p[r][a] = 0.0f;

    float acc[4][8][4];
#pragma unroll
    for (int mi = 0; mi < 4; ++mi)
#pragma unroll
        for (int nj = 0; nj < 8; ++nj)
#pragma unroll
            for (int q = 0; q < 4; ++q) acc[mi][nj][q] = 0.0f;

    auto issue = [&](int it) {
        if (it >= ITERS) return;
        const int nt = it >> 4, kc = it & 15;
        int st = it % STAGES;
        const uint32_t sA = sb + st * STAGE_BYTES;
        const uint32_t sB = sA + A_BYTES;
        const uint32_t ko = (uint32_t)kc * BK;
#pragma unroll
        for (int i = 0; i < 8; ++i)
            CP_ASYNC16(sA + sA0 + 2048u * i, (const char*)(g_Sbf + a_goff[i] + ko));
        const uint32_t boff = bNtBase + (uint32_t)(nt * BN) * Sdim + ko + b_g0;
#pragma unroll
        for (int i = 0; i < 8; ++i)
            CP_ASYNC16(sB + sA0 + 2048u * i, (const char*)(g_W1T + boff + (uint32_t)(i * 16) * Sdim));
        CP_COMMIT();
    };

    issue(0); issue(1);

    float* logit = (float*)(smp + OFF_LOGIT);
    for (int i = tid; i < BM * 4; i += NTHREADS) logit[i] = 0.0f;

    for (int it = 0; it < ITERS; ++it) {
        CP_WAIT(1);
        __syncthreads();
        issue(it + STAGES - 1);

        const int st = it % STAGES;
        const uint32_t sA = sb + st * STAGE_BYTES;
        const uint32_t sB = sA + A_BYTES;
#pragma unroll
        for (int ks = 0; ks < 4; ++ks) {
            uint32_t afr[4][4], bfr[4][4];
#pragma unroll
            for (int mi = 0; mi < 4; ++mi)
                ldsm4(afr[mi], sA + swz(aRow[mi] + (uint32_t)(ks * 32) + aCol));
#pragma unroll
            for (int s = 0; s < 4; ++s)
                ldsm4(bfr[s], sB + swz(bRow[s] + (uint32_t)(ks * 32) + bCol));
#pragma unroll
            for (int mi = 0; mi < 4; ++mi)
#pragma unroll
                for (int s = 0; s < 4; ++s) {
                    mma16816(acc[mi][2 * s    ], afr[mi], bfr[s][0], bfr[s][1]);
                    mma16816(acc[mi][2 * s + 1], afr[mi], bfr[s][2], bfr[s][3]);
                }
        }

        // ---- per-nt fused epilogue ----
        if ((it & 15) == 15) {
            const int ntg = ntBase + (it >> 4);
#pragma unroll
            for (int nj = 0; nj < 8; ++nj) {
                const int cbase = ntg * BN + wn + 8 * nj + 2 * (lid & 3);
                const float b1a = __ldg(b1 + cbase);
                const float b1b = __ldg(b1 + cbase + 1);
                float w2a[4], w2b[4];
#pragma unroll
                for (int a = 0; a < 4; ++a) {
                    w2a[a] = __ldg(W2 + (size_t)cbase * W2LD + a);
                    w2b[a] = __ldg(W2 + (size_t)(cbase + 1) * W2LD + a);
                }
#pragma unroll
                for (int mi = 0; mi < 4; ++mi) {
                    float h0 = fmaxf(acc[mi][nj][0] + b1a, 0.0f);
                    float h1 = fmaxf(acc[mi][nj][1] + b1b, 0.0f);
                    float h2 = fmaxf(acc[mi][nj][2] + b1a, 0.0f);
                    float h3 = fmaxf(acc[mi][nj][3] + b1b, 0.0f);
#pragma unroll
                    for (int a = 0; a < 4; ++a) {
                        p[2 * mi    ][a] += h0 * w2a[a] + h1 * w2b[a];
                        p[2 * mi + 1][a] += h2 * w2a[a] + h3 * w2b[a];
                    }
                }
            }
#pragma unroll
            for (int mi = 0; mi < 4; ++mi)
#pragma unroll
                for (int nj = 0; nj < 8; ++nj)
#pragma unroll
                    for (int q = 0; q < 4; ++q) acc[mi][nj][q] = 0.0f;
        }
    }

    // ---- reduce partial logits in smem, then global atomics ----
    __syncthreads();
#pragma unroll
    for (int pr = 0; pr < 8; ++pr) {
        int row = wm + 16 * (pr >> 1) + (lid >> 2) + 8 * (pr & 1);
#pragma unroll
        for (int a = 0; a < 4; ++a)
            atomicAdd(&logit[row * 4 + a], p[pr][a]);
    }
    __syncthreads();
    if (tid < BM && R0 + tid < R) {
#pragma unroll
        for (int a = 0; a < 4; ++a)
            atomicAdd(&g_logit[(size_t)(R0 + tid) * 4 + a], logit[tid * 4 + a]);
    }
}

// ---------------- finalize over compact rows ----------------
__global__ void traj_finalize_kernel(const int* __restrict__ actions,
                                     const float* __restrict__ b2,
                                     float* __restrict__ out)
{
    int i = blockIdx.x * 128 + threadIdx.x;
    float local = 0.0f;
    if (i < g_nrows) {
        int m  = g_rowmap[i];
        int bb = m >> 9;            // TP1 = 512
        int tt = m & 511;
        size_t o = (size_t)i * 4;
        float l0 = g_logit[o + 0] + b2[0];
        float l1 = g_logit[o + 1] + b2[1];
        float l2 = g_logit[o + 2] + b2[2];
        float l3 = g_logit[o + 3] + b2[3];
        float mx = fmaxf(fmaxf(l0, l1), fmaxf(l2, l3));
        float lse = mx + logf(expf(l0 - mx) + expf(l1 - mx) + expf(l2 - mx) + expf(l3 - mx));
        int act = actions[bb * MAXT + tt];
        float la = (act == 0) ? l0 : (act == 1) ? l1 : (act == 2) ? l2 : l3;
        local = lse - la;
    }
#pragma unroll
    for (int o = 16; o > 0; o >>= 1)
        local += __shfl_xor_sync(0xFFFFFFFFu, local, o);
    if ((threadIdx.x & 31) == 0 && local != 0.0f) atomicAdd(out, local);
}

// ---------------- launch ----------------
extern "C" void kernel_launch(void* const* d_in, const int* in_sizes, int n_in,
                              void* d_out, int out_size) {
    const float* s       = (const float*)d_in[0];
    const int*   actions = (const int*)  d_in[1];
    const int*   lengths = (const int*)  d_in[2];
    const float* W1      = (const float*)d_in[3];
    const float* b1      = (const float*)d_in[4];
    const float* W2      = (const float*)d_in[5];
    const float* b2      = (const float*)d_in[6];
    float* out = (float*)d_out;

    cudaFuncSetAttribute(traj_mma_kernel, cudaFuncAttributeMaxDynamicSharedMemorySize, SMEM_BYTES);

    compact_kernel<<<1, 256>>>(lengths, out);
    conv_S_compact<<<2048, 256>>>(s);
    conv_W1T_kernel<<<dim3(Hdim / 32, Sdim / 32), dim3(32, 8)>>>(W1);
    traj_mma_kernel<<<NTILES * NCHUNK, NTHREADS, SMEM_BYTES>>>(b1, W2);
    traj_finalize_kernel<<<(ROWS_TOTAL + 127) / 128, 128>>>(actions, b2, out);
}